// round 11
// baseline (speedup 1.0000x reference)
#include <cuda_runtime.h>
#include <math.h>

#define NB   8
#define NT   128
#define NS   400
#define NH   256
#define NVOC 50257
#define NBT  (NB * NT)
#define BMW  1572              // bitmap words per batch: ceil(50257/32)=1571, +1 pad
#define HSZ  1024              // dedup hash table slots (power of two)

// ---------------- scratch (__device__ globals; no allocation allowed) --------
__device__ float2   g_coeff[NBT];       // per (b,t): {p_gen, -(1-p)*lse}
__device__ float    g_corr[NBT * NS];   // per (b,t,head s): (1-p)*c_v  (heads only)
__device__ unsigned g_bm[NB * BMW];     // per-b bitmap of touched vocab ids
__device__ short    g_sidx[NB * NVOC];  // per-b map: vocab id -> head slot (valid where bit set)

// ---------------- block reductions: warp shuffle + 8-partial broadcast -------
__device__ __forceinline__ float block_sum_256(float v, float* red) {
    #pragma unroll
    for (int o = 16; o; o >>= 1) v += __shfl_xor_sync(0xffffffffu, v, o);
    if ((threadIdx.x & 31) == 0) red[threadIdx.x >> 5] = v;
    __syncthreads();
    float tot = red[0] + red[1] + red[2] + red[3] + red[4] + red[5] + red[6] + red[7];
    __syncthreads();
    return tot;
}
__device__ __forceinline__ float block_max_256(float v, float* red) {
    #pragma unroll
    for (int o = 16; o; o >>= 1) v = fmaxf(v, __shfl_xor_sync(0xffffffffu, v, o));
    if ((threadIdx.x & 31) == 0) red[threadIdx.x >> 5] = v;
    __syncthreads();
    float m = fmaxf(fmaxf(fmaxf(red[0], red[1]), fmaxf(red[2], red[3])),
                    fmaxf(fmaxf(red[4], red[5]), fmaxf(red[6], red[7])));
    __syncthreads();
    return m;
}

// ---------------- kernel 1: fused dedup + p_gen + grouped-sum + lse ----------
// Each block (one (b,t) row) rebuilds the per-batch dedup hash table locally
// in smem (tokens are 1.6 KB / batch, L2-hot across the 128 blocks sharing
// them; build is a few hundred cycles of smem atomics). The block with
// bt % NT == 0 also publishes the batch's bitmap + vocab->slot map for mix.
__global__ __launch_bounds__(256)
void rowstats_kernel(const int*   __restrict__ tokens,
                     const float* __restrict__ ctx,
                     const float* __restrict__ din,
                     const float* __restrict__ dout,
                     const float* __restrict__ attn,
                     const float* __restrict__ Wc, const float* __restrict__ bc,
                     const float* __restrict__ Wo, const float* __restrict__ bo,
                     const float* __restrict__ Wi, const float* __restrict__ bi) {
    const int bt  = blockIdx.x;
    const int b   = bt >> 7;            // bt / NT
    const int tid = threadIdx.x;

    __shared__ float red[8];
    __shared__ float c_sm[NS];
    __shared__ int   hkey[HSZ];
    __shared__ int   hrep[HSZ];
    __shared__ int   cnt;

    // --- init hash table + accumulators ---
    #pragma unroll
    for (int i = tid; i < HSZ; i += 256) { hkey[i] = -1; hrep[i] = 0x7fffffff; }
    c_sm[tid] = 0.0f;
    if (tid < NS - 256) c_sm[tid + 256] = 0.0f;
    if (tid == 0) cnt = 0;
    __syncthreads();

    // --- build: insert this batch's tokens (slots tid and tid+256) ---
    const int tok0 = tokens[b * NS + tid];
    int tok1 = -1;
    {
        unsigned h = ((unsigned)tok0 * 2654435761u) & (HSZ - 1u);
        for (;;) {
            const int old = atomicCAS(&hkey[h], -1, tok0);
            if (old == -1 || old == tok0) break;
            h = (h + 1u) & (HSZ - 1u);
        }
        atomicMin(&hrep[h], tid);
    }
    if (tid < NS - 256) {
        tok1 = tokens[b * NS + tid + 256];
        unsigned h = ((unsigned)tok1 * 2654435761u) & (HSZ - 1u);
        for (;;) {
            const int old = atomicCAS(&hkey[h], -1, tok1);
            if (old == -1 || old == tok1) break;
            h = (h + 1u) & (HSZ - 1u);
        }
        atomicMin(&hrep[h], tid + 256);
    }

    // --- p_gen partial while the table settles ---
    const int base = bt * NH + tid;
    float partial = ctx[base]  * Wc[tid]
                  + dout[base] * Wo[tid]
                  + din[base]  * Wi[tid];
    __syncthreads();

    // --- probe: canonical head per slot (plain reads; table is final) ---
    unsigned hh = ((unsigned)tok0 * 2654435761u) & (HSZ - 1u);
    while (hkey[hh] != tok0) hh = (hh + 1u) & (HSZ - 1u);
    const int h0 = hrep[hh];
    int h1 = -1;
    if (tid < NS - 256) {
        unsigned h = ((unsigned)tok1 * 2654435761u) & (HSZ - 1u);
        while (hkey[h] != tok1) h = (h + 1u) & (HSZ - 1u);
        h1 = hrep[h];
    }

    const float z = block_sum_256(partial, red) + bc[0] + bo[0] + bi[0];
    const float p = 1.0f / (1.0f + expf(-z));
    const float q = 1.0f - p;

    // --- group attn values by canonical head ---
    atomicAdd(&c_sm[h0], attn[bt * NS + tid]);
    if (tid < NS - 256) atomicAdd(&c_sm[h1], attn[bt * NS + tid + 256]);
    __syncthreads();

    const bool head0 = (h0 == tid);
    const bool head1 = (h1 == tid + 256);
    const float c0 = head0 ? c_sm[tid]       : 0.0f;
    const float c1 = head1 ? c_sm[tid + 256] : 0.0f;
    if (head0) atomicAdd(&cnt, 1);
    if (head1) atomicAdd(&cnt, 1);

    // --- max over row (implicit zeros make 0 a valid floor; c >= 0 anyway) ---
    float m = 0.0f;
    if (head0) m = fmaxf(m, c0);
    if (head1) m = fmaxf(m, c1);
    m = block_max_256(m, red);

    // --- sumexp over heads + (V - n) zeros ---
    float se = 0.0f;
    if (head0) se += expf(c0 - m);
    if (head1) se += expf(c1 - m);
    se = block_sum_256(se, red);   // cnt's atomicAdds are pre-barrier: visible after

    if (tid == 0) {
        const float total = se + (float)(NVOC - cnt) * expf(-m);
        const float lse = m + logf(total);
        g_coeff[bt] = make_float2(p, -q * lse);
    }

    // --- correction values for fused-mix lookup ---
    if (head0) g_corr[bt * NS + tid]       = q * c0;
    if (head1) g_corr[bt * NS + tid + 256] = q * c1;

    // --- designated block per batch publishes bitmap + slot map ---
    if ((bt & (NT - 1)) == 0) {
        #pragma unroll
        for (int i = tid; i < BMW; i += 256) g_bm[b * BMW + i] = 0u;
        __syncthreads();
        if (head0) {
            atomicOr(&g_bm[b * BMW + ((unsigned)tok0 >> 5)], 1u << (tok0 & 31));
            g_sidx[b * NVOC + tok0] = (short)tid;
        }
        if (head1) {
            atomicOr(&g_bm[b * BMW + ((unsigned)tok1 >> 5)], 1u << (tok1 & 31));
            g_sidx[b * NVOC + tok1] = (short)(tid + 256);
        }
    }
}

// ---------------- kernel 2: streaming affine mix + fused sparse correction ---
// total elements = NBT*NVOC = 51,463,168 = 50257 * 1024 -> exactly
// 12,865,792 float4s = 50257 blocks * 256 threads. No bounds checks.
__global__ __launch_bounds__(256)
void mix_kernel(const float4* __restrict__ vocab, float4* __restrict__ out) {
    const unsigned i4   = blockIdx.x * 256u + threadIdx.x;
    const unsigned base = i4 * 4u;
    const float4 v = __ldcs(&vocab[i4]);      // streaming read: don't pollute L2

    const unsigned bt0 = base / (unsigned)NVOC;
    const unsigned rem = base - bt0 * (unsigned)NVOC;

    float4 o;
    if (rem <= (unsigned)(NVOC - 4)) {
        // entire float4 inside one row (the overwhelmingly common case)
        const float2 cf = g_coeff[bt0];
        o.x = fmaf(v.x, cf.x, cf.y);
        o.y = fmaf(v.y, cf.x, cf.y);
        o.z = fmaf(v.z, cf.x, cf.y);
        o.w = fmaf(v.w, cf.x, cf.y);

        // fused copy-dist correction: bitmap gate (L2-hot, 50 KB total)
        const unsigned b = bt0 >> 7;                 // bt / NT
        const unsigned* __restrict__ bm = g_bm + b * BMW;
        const unsigned w0 = rem >> 5;
        const unsigned sh = rem & 31u;
        unsigned bits = bm[w0] >> sh;
        if (sh > 28u) bits |= bm[w0 + 1] << (32u - sh);
        bits &= 15u;
        if (bits) {
            const short* __restrict__ sx   = g_sidx + b * NVOC;
            const float* __restrict__ corr = g_corr + bt0 * NS;
            if (bits & 1u) o.x += corr[sx[rem + 0u]];
            if (bits & 2u) o.y += corr[sx[rem + 1u]];
            if (bits & 4u) o.z += corr[sx[rem + 2u]];
            if (bits & 8u) o.w += corr[sx[rem + 3u]];
        }
    } else {
        // straddles a row boundary (V odd): fully general per-element path (rare)
        float vv[4] = {v.x, v.y, v.z, v.w};
        float oo[4];
        #pragma unroll
        for (int i = 0; i < 4; ++i) {
            const unsigned g  = base + (unsigned)i;
            const unsigned bt = g / (unsigned)NVOC;
            const unsigned r  = g - bt * (unsigned)NVOC;
            const unsigned b  = bt >> 7;
            const float2 cf = g_coeff[bt];
            float val = fmaf(vv[i], cf.x, cf.y);
            if ((g_bm[b * BMW + (r >> 5)] >> (r & 31u)) & 1u)
                val += g_corr[bt * NS + g_sidx[b * NVOC + r]];
            oo[i] = val;
        }
        o.x = oo[0]; o.y = oo[1]; o.z = oo[2]; o.w = oo[3];
    }
    __stcs(&out[i4], o);                      // streaming write
}

// ---------------- launch ------------------------------------------------------
extern "C" void kernel_launch(void* const* d_in, const int* in_sizes, int n_in,
                              void* d_out, int out_size) {
    const int*   tokens = (const int*)  d_in[0];   // [B, S]
    const float* ctx    = (const float*)d_in[1];   // [B, T, H]
    const float* din    = (const float*)d_in[2];   // [B, T, H]
    const float* dout   = (const float*)d_in[3];   // [B, T, H]
    const float* vocab  = (const float*)d_in[4];   // [B, T, V]
    const float* attn   = (const float*)d_in[5];   // [B, T, S]
    // d_in[6] = encoder_outputs (unused by reference)
    const float* Wc = (const float*)d_in[7];
    const float* bc = (const float*)d_in[8];
    const float* Wo = (const float*)d_in[9];
    const float* bo = (const float*)d_in[10];
    const float* Wi = (const float*)d_in[11];
    const float* bi = (const float*)d_in[12];
    float* out = (float*)d_out;

    rowstats_kernel<<<NBT, 256>>>(tokens, ctx, din, dout, attn,
                                  Wc, bc, Wo, bo, Wi, bi);
    mix_kernel<<<NVOC, 256>>>((const float4*)vocab, (float4*)out);
}